// round 11
// baseline (speedup 1.0000x reference)
#include <cuda_runtime.h>
#include <cstddef>

#define N_NODES 200000
#define N_EDGES 3200000
#define N_GRAPHS 64
#define HID 32
#define HEADS 4

// ---------------- scratch (device globals; no allocation allowed) ----------------
__device__ float g_f[(size_t)N_NODES * HID];      // fc features (both layers)
__device__ float g_er[(size_t)N_NODES * HEADS];   // per-head er
__device__ float g_acc0[(size_t)N_NODES * HID];
__device__ float g_den0[(size_t)N_NODES * 8];     // den, x2-duplicated per head (slot=sub)
__device__ float g_acc1[(size_t)N_NODES * HID];
__device__ float g_den1[(size_t)N_NODES * 8];
__device__ float g_sums[N_GRAPHS * HID];
__device__ float g_cnt[N_GRAPHS];

__device__ __forceinline__ void red_add_v4(float* addr, float4 v) {
    asm volatile("red.global.add.v4.f32 [%0], {%1,%2,%3,%4};"
                 :: "l"(addr), "f"(v.x), "f"(v.y), "f"(v.z), "f"(v.w)
                 : "memory");
}
__device__ __forceinline__ void red_add_f(float* addr, float v) {
    asm volatile("red.global.add.f32 [%0], %1;" :: "l"(addr), "f"(v) : "memory");
}

// ---------------- K0: thread-per-node, chunked + vectorized: h = emb[node_ids]; f = h@W0; er; zero acc0/den0 ----------------
// 4 chunks of 8 outputs (chunk == head): f[32] never fully live (regs ~52),
// and weights load as LDS.128 (round-10 regression was scalar LDS here).
__global__ void __launch_bounds__(128) k_gather_fc(
        const int* __restrict__ node_ids,
        const float* __restrict__ emb,
        const float* __restrict__ W,
        const float* __restrict__ ar) {
    __shared__ float sW[HID * HID];
    __shared__ float sar[HID];
    int tid = threadIdx.x;
    for (int i = tid; i < HID * HID; i += 128) sW[i] = W[i];
    if (tid < HID) sar[tid] = ar[tid];
    __syncthreads();

    int n = blockIdx.x * 128 + tid;
    if (n >= N_NODES) return;

    int nid = __ldg(node_ids + n);
    const float4* hrow = (const float4*)(emb + (size_t)nid * HID);
    float h[HID];
#pragma unroll
    for (int i = 0; i < 8; i++) {
        float4 v = __ldg(hrow + i);
        h[4 * i] = v.x; h[4 * i + 1] = v.y; h[4 * i + 2] = v.z; h[4 * i + 3] = v.w;
    }
    float4* fout = (float4*)(g_f + (size_t)n * HID);
    float4* aout = (float4*)(g_acc0 + (size_t)n * HID);
    const float4 z4 = make_float4(0.f, 0.f, 0.f, 0.f);
#pragma unroll
    for (int c = 0; c < 4; c++) {                 // chunk c = head c (outputs 8c..8c+7)
        float4 fa = z4, fb = z4;
#pragma unroll
        for (int k = 0; k < HID; k++) {
            float hk = h[k];
            const float4* wr = (const float4*)(sW + k * HID) + 2 * c;
            float4 w0 = wr[0];
            float4 w1 = wr[1];
            fa.x = fmaf(hk, w0.x, fa.x); fa.y = fmaf(hk, w0.y, fa.y);
            fa.z = fmaf(hk, w0.z, fa.z); fa.w = fmaf(hk, w0.w, fa.w);
            fb.x = fmaf(hk, w1.x, fb.x); fb.y = fmaf(hk, w1.y, fb.y);
            fb.z = fmaf(hk, w1.z, fb.z); fb.w = fmaf(hk, w1.w, fb.w);
        }
        fout[2 * c]     = fa;
        fout[2 * c + 1] = fb;
        aout[2 * c] = z4; aout[2 * c + 1] = z4;
        float er = fa.x * sar[c * 8]     + fa.y * sar[c * 8 + 1]
                 + fa.z * sar[c * 8 + 2] + fa.w * sar[c * 8 + 3]
                 + fb.x * sar[c * 8 + 4] + fb.y * sar[c * 8 + 5]
                 + fb.z * sar[c * 8 + 6] + fb.w * sar[c * 8 + 7];
        g_er[n * HEADS + c] = er;
    }
    ((float4*)g_den0)[n * 2] = z4;
    ((float4*)g_den0)[n * 2 + 1] = z4;
}

// ---------------- K1/K3: edge pass — 4-wf/edge (round-10 engine, unchanged: measured 114us) ----------------
__global__ void __launch_bounds__(256, 8) k_edge(
        const int* __restrict__ src, const int* __restrict__ dst,
        const float* __restrict__ al,
        float* __restrict__ acc, float* __restrict__ den) {
    int lane = threadIdx.x & 31;
    int warp = (blockIdx.x * blockDim.x + threadIdx.x) >> 5;
    int nwarp = (gridDim.x * blockDim.x) >> 5;
    int sub = lane & 7;       // float4 slot within the 32-float row
    int grp = lane >> 3;      // which of the 4 edges this lane serves
    int head = sub >> 1;      // head of this slot
    const float4* f4 = (const float4*)g_f;
    float4 sal = __ldg(((const float4*)al) + sub);

    for (int base = warp * 32; base < N_EDGES; base += nwarp * 32) {
        int e = base + lane;                      // N_EDGES % 32 == 0
        int s = __ldg(src + e);
        int d = __ldg(dst + e);

#pragma unroll
        for (int r = 0; r < 8; r++) {
            int idx = r * 4 + grp;
            int s_r = __shfl_sync(0xffffffffu, s, idx);
            int d_r = __shfl_sync(0xffffffffu, d, idx);

            float er_h = __ldg(g_er + d_r * HEADS + head);      // 8 lanes, 1 line
            float4 fv = __ldg(f4 + s_r * 8 + sub);              // 128B row, 1 wf
            float part = fv.x * sal.x + fv.y * sal.y + fv.z * sal.z + fv.w * sal.w;
            float el_h = part + __shfl_xor_sync(0xffffffffu, part, 1);

            float x = el_h + er_h;
            x = x > 0.f ? x : 0.2f * x;           // leaky_relu(0.2)
            float ex = __expf(x);

            red_add_v4(acc + d_r * 32 + sub * 4,
                       make_float4(ex * fv.x, ex * fv.y, ex * fv.z, ex * fv.w));
            red_add_f(den + d_r * 8 + sub, ex);   // own slot, no shuffles
        }
    }
}

// ---------------- K2: thread-per-node, chunked + vectorized: h1 = relu(acc0/den0+b0); f1 = h1@W1; er1; zero acc1/den1/sums ----------------
__global__ void __launch_bounds__(128) k_node_mid(
        const float* __restrict__ b0,
        const float* __restrict__ W,
        const float* __restrict__ ar) {
    __shared__ float sW[HID * HID];
    __shared__ float sar[HID], sb[HID];
    int tid = threadIdx.x;
    for (int i = tid; i < HID * HID; i += 128) sW[i] = W[i];
    if (tid < HID) { sar[tid] = ar[tid]; sb[tid] = b0[tid]; }
    __syncthreads();

    int n = blockIdx.x * 128 + tid;
    if (n < N_GRAPHS * HID) g_sums[n] = 0.f;
    if (n < N_GRAPHS) g_cnt[n] = 0.f;
    if (n >= N_NODES) return;

    float h[HID];
    const float4* arow = (const float4*)(g_acc0 + (size_t)n * HID);
#pragma unroll
    for (int hh = 0; hh < HEADS; hh++) {
        float dv = g_den0[(size_t)n * 8 + 2 * hh];
        float inv = dv > 0.f ? __fdividef(1.f, dv) : 0.f;
        float4 v0 = arow[2 * hh];
        float4 v1 = arow[2 * hh + 1];
        h[8 * hh]     = fmaxf(fmaf(v0.x, inv, sb[8 * hh]),     0.f);
        h[8 * hh + 1] = fmaxf(fmaf(v0.y, inv, sb[8 * hh + 1]), 0.f);
        h[8 * hh + 2] = fmaxf(fmaf(v0.z, inv, sb[8 * hh + 2]), 0.f);
        h[8 * hh + 3] = fmaxf(fmaf(v0.w, inv, sb[8 * hh + 3]), 0.f);
        h[8 * hh + 4] = fmaxf(fmaf(v1.x, inv, sb[8 * hh + 4]), 0.f);
        h[8 * hh + 5] = fmaxf(fmaf(v1.y, inv, sb[8 * hh + 5]), 0.f);
        h[8 * hh + 6] = fmaxf(fmaf(v1.z, inv, sb[8 * hh + 6]), 0.f);
        h[8 * hh + 7] = fmaxf(fmaf(v1.w, inv, sb[8 * hh + 7]), 0.f);
    }

    float4* fout = (float4*)(g_f + (size_t)n * HID);
    float4* aout = (float4*)(g_acc1 + (size_t)n * HID);
    const float4 z4 = make_float4(0.f, 0.f, 0.f, 0.f);
#pragma unroll
    for (int c = 0; c < 4; c++) {
        float4 fa = z4, fb = z4;
#pragma unroll
        for (int k = 0; k < HID; k++) {
            float hk = h[k];
            const float4* wr = (const float4*)(sW + k * HID) + 2 * c;
            float4 w0 = wr[0];
            float4 w1 = wr[1];
            fa.x = fmaf(hk, w0.x, fa.x); fa.y = fmaf(hk, w0.y, fa.y);
            fa.z = fmaf(hk, w0.z, fa.z); fa.w = fmaf(hk, w0.w, fa.w);
            fb.x = fmaf(hk, w1.x, fb.x); fb.y = fmaf(hk, w1.y, fb.y);
            fb.z = fmaf(hk, w1.z, fb.z); fb.w = fmaf(hk, w1.w, fb.w);
        }
        fout[2 * c]     = fa;
        fout[2 * c + 1] = fb;
        aout[2 * c] = z4; aout[2 * c + 1] = z4;
        float er = fa.x * sar[c * 8]     + fa.y * sar[c * 8 + 1]
                 + fa.z * sar[c * 8 + 2] + fa.w * sar[c * 8 + 3]
                 + fb.x * sar[c * 8 + 4] + fb.y * sar[c * 8 + 5]
                 + fb.z * sar[c * 8 + 6] + fb.w * sar[c * 8 + 7];
        g_er[n * HEADS + c] = er;
    }
    ((float4*)g_den1)[n * 2] = z4;
    ((float4*)g_den1)[n * 2 + 1] = z4;
}

// ---------------- K4: h2 + run-length pooled per-graph sums (graph_ids sorted) ----------------
__global__ void k_pool(const int* __restrict__ graph_ids,
                       const float* __restrict__ b1) {
    int lane = threadIdx.x & 31;
    int warp = (blockIdx.x * blockDim.x + threadIdx.x) >> 5;
    int nwarp = (gridDim.x * blockDim.x) >> 5;
    int dslot = (lane >> 3) << 1;
    float bl = __ldg(b1 + lane);
    int nchunk = (N_NODES + 31) / 32;
    for (int c = warp; c < nchunk; c += nwarp) {
        int base = c * 32;
        int lim = min(32, N_NODES - base);
        float runsum = 0.f;
        int rung = __ldg(graph_ids + base);
        int runcnt = 0;
        for (int i = 0; i < lim; i++) {
            int n = base + i;
            int gid = __ldg(graph_ids + n);            // uniform across warp
            float dv = g_den1[(size_t)n * 8 + dslot];
            float v  = g_acc1[(size_t)n * HID + lane];
            float hv = dv > 0.f ? __fdividef(v, dv) : 0.f;
            hv = fmaxf(hv + bl, 0.f);
            if (gid != rung) {
                atomicAdd(g_sums + rung * HID + lane, runsum);
                if (lane == 0) atomicAdd(g_cnt + rung, (float)runcnt);
                runsum = 0.f; runcnt = 0; rung = gid;
            }
            runsum += hv; runcnt++;
        }
        atomicAdd(g_sums + rung * HID + lane, runsum);
        if (lane == 0) atomicAdd(g_cnt + rung, (float)runcnt);
    }
}

// ---------------- K5: scorer MLP ----------------
__global__ void k_score(const float* __restrict__ sw1, const float* __restrict__ sb1,
                        const float* __restrict__ sw2, const float* __restrict__ sb2,
                        float* __restrict__ out) {
    __shared__ float s1[HID * HID];
    __shared__ float sb[HID], s2[HID];
    int t = threadIdx.x;
    for (int i = t; i < HID * HID; i += blockDim.x) s1[i] = sw1[i];
    if (t < HID) { sb[t] = sb1[t]; s2[t] = sw2[t]; }
    __syncthreads();
    if (t < N_GRAPHS) {
        float c = fmaxf(g_cnt[t], 1.f);
        float invc = __fdividef(1.f, c);
        float hg[HID];
#pragma unroll
        for (int k = 0; k < HID; k++) hg[k] = g_sums[t * HID + k] * invc;
        float score = __ldg(sb2);
#pragma unroll
        for (int j = 0; j < HID; j++) {
            float a = sb[j];
#pragma unroll
            for (int k = 0; k < HID; k++) a += hg[k] * s1[k * HID + j];
            a = fmaxf(a, 0.f);
            score += a * s2[j];
        }
        out[t] = score;
    }
}

// ---------------- launch ----------------
extern "C" void kernel_launch(void* const* d_in, const int* in_sizes, int n_in,
                              void* d_out, int out_size) {
    const int*   node_ids = (const int*)d_in[0];
    const int*   src      = (const int*)d_in[1];
    const int*   dst      = (const int*)d_in[2];
    const int*   gids     = (const int*)d_in[3];
    const float* emb      = (const float*)d_in[4];
    const float* W0       = (const float*)d_in[5];
    const float* al0      = (const float*)d_in[6];
    const float* ar0      = (const float*)d_in[7];
    const float* b0       = (const float*)d_in[8];
    const float* W1       = (const float*)d_in[9];
    const float* al1      = (const float*)d_in[10];
    const float* ar1      = (const float*)d_in[11];
    const float* b1       = (const float*)d_in[12];
    const float* sw1      = (const float*)d_in[13];
    const float* sb1      = (const float*)d_in[14];
    const float* sw2      = (const float*)d_in[15];
    const float* sb2      = (const float*)d_in[16];
    float* out = (float*)d_out;

    void *acc0, *den0, *acc1, *den1;
    cudaGetSymbolAddress(&acc0, g_acc0);
    cudaGetSymbolAddress(&den0, g_den0);
    cudaGetSymbolAddress(&acc1, g_acc1);
    cudaGetSymbolAddress(&den1, g_den1);

    const int nodeBlocks = (N_NODES + 127) / 128;

    k_gather_fc<<<nodeBlocks, 128>>>(node_ids, emb, W0, ar0);
    k_edge<<<2048, 256>>>(src, dst, al0, (float*)acc0, (float*)den0);
    k_node_mid<<<nodeBlocks, 128>>>(b0, W1, ar1);
    k_edge<<<2048, 256>>>(src, dst, al1, (float*)acc1, (float*)den1);
    k_pool<<<(6250 + 7) / 8, 256>>>(gids, b1);
    k_score<<<1, 64>>>(sw1, sb1, sw2, sb2, out);
}

// round 12
// speedup vs baseline: 1.1151x; 1.1151x over previous
#include <cuda_runtime.h>
#include <cstddef>

#define N_NODES 200000
#define N_EDGES 3200000
#define N_GRAPHS 64
#define HID 32
#define HEADS 4
#define EDGES_PER_WARP 256        // 64 contiguous edges per 8-lane group
#define NWARPS (N_EDGES / EDGES_PER_WARP)   // 12500

// ---------------- scratch (device globals; no allocation allowed) ----------------
__device__ float g_f[(size_t)N_NODES * HID];      // fc features (both layers)
__device__ float g_er[(size_t)N_NODES * HEADS];   // per-head er
__device__ float g_acc0[(size_t)N_NODES * HID];
__device__ float g_den0[(size_t)N_NODES * 8];     // den, x2-duplicated per head (slot=sub)
__device__ float g_acc1[(size_t)N_NODES * HID];
__device__ float g_den1[(size_t)N_NODES * 8];
__device__ float g_sums[N_GRAPHS * HID];
__device__ float g_cnt[N_GRAPHS];
// dst-sorted edge stream (built once per launch, used by both layers)
__device__ int g_deg[N_NODES];
__device__ int g_cur[N_NODES];
__device__ int g_total;
__device__ int g_ss[N_EDGES];                     // src, sorted by dst
__device__ int g_ds[N_EDGES];                     // dst, sorted (filled from row_ptr)

// REDs WITHOUT memory clobber: red.global has no ordering requirement (atomic,
// result only read after kernel end); the clobber was blocking f-load hoisting
// across flushes and serializing the sorted engine.
__device__ __forceinline__ void red_add_v4(float* addr, float4 v) {
    asm volatile("red.global.add.v4.f32 [%0], {%1,%2,%3,%4};"
                 :: "l"(addr), "f"(v.x), "f"(v.y), "f"(v.z), "f"(v.w));
}
__device__ __forceinline__ void red_add_f(float* addr, float v) {
    asm volatile("red.global.add.f32 [%0], %1;" :: "l"(addr), "f"(v));
}

// ---------------- K0: thread-per-node, chunked+vectorized (round-11, frozen); also zero deg/total ----------------
__global__ void __launch_bounds__(128) k_gather_fc(
        const int* __restrict__ node_ids,
        const float* __restrict__ emb,
        const float* __restrict__ W,
        const float* __restrict__ ar) {
    __shared__ float sW[HID * HID];
    __shared__ float sar[HID];
    int tid = threadIdx.x;
    for (int i = tid; i < HID * HID; i += 128) sW[i] = W[i];
    if (tid < HID) sar[tid] = ar[tid];
    __syncthreads();

    int n = blockIdx.x * 128 + tid;
    if (n == 0) g_total = 0;
    if (n >= N_NODES) return;
    g_deg[n] = 0;

    int nid = __ldg(node_ids + n);
    const float4* hrow = (const float4*)(emb + (size_t)nid * HID);
    float h[HID];
#pragma unroll
    for (int i = 0; i < 8; i++) {
        float4 v = __ldg(hrow + i);
        h[4 * i] = v.x; h[4 * i + 1] = v.y; h[4 * i + 2] = v.z; h[4 * i + 3] = v.w;
    }
    float4* fout = (float4*)(g_f + (size_t)n * HID);
    float4* aout = (float4*)(g_acc0 + (size_t)n * HID);
    const float4 z4 = make_float4(0.f, 0.f, 0.f, 0.f);
#pragma unroll
    for (int c = 0; c < 4; c++) {                 // chunk c = head c
        float4 fa = z4, fb = z4;
#pragma unroll
        for (int k = 0; k < HID; k++) {
            float hk = h[k];
            const float4* wr = (const float4*)(sW + k * HID) + 2 * c;
            float4 w0 = wr[0];
            float4 w1 = wr[1];
            fa.x = fmaf(hk, w0.x, fa.x); fa.y = fmaf(hk, w0.y, fa.y);
            fa.z = fmaf(hk, w0.z, fa.z); fa.w = fmaf(hk, w0.w, fa.w);
            fb.x = fmaf(hk, w1.x, fb.x); fb.y = fmaf(hk, w1.y, fb.y);
            fb.z = fmaf(hk, w1.z, fb.z); fb.w = fmaf(hk, w1.w, fb.w);
        }
        fout[2 * c]     = fa;
        fout[2 * c + 1] = fb;
        aout[2 * c] = z4; aout[2 * c + 1] = z4;
        float er = fa.x * sar[c * 8]     + fa.y * sar[c * 8 + 1]
                 + fa.z * sar[c * 8 + 2] + fa.w * sar[c * 8 + 3]
                 + fb.x * sar[c * 8 + 4] + fb.y * sar[c * 8 + 5]
                 + fb.z * sar[c * 8 + 6] + fb.w * sar[c * 8 + 7];
        g_er[n * HEADS + c] = er;
    }
    ((float4*)g_den0)[n * 2] = z4;
    ((float4*)g_den0)[n * 2 + 1] = z4;
}

// ---------------- build: count -> assign(+ds fill) -> scatter (ss only) ----------------
__global__ void k_count(const int* __restrict__ dst) {
    int e = blockIdx.x * blockDim.x + threadIdx.x;
    if (e < N_EDGES) atomicAdd(&g_deg[__ldg(dst + e)], 1);
}

// Warp-aggregated range assignment + fill ds[start..start+deg) = n.
// Block order arbitrary; ranges disjoint, per-dst edges contiguous — sufficient.
__global__ void k_assign_fill() {
    int n = blockIdx.x * blockDim.x + threadIdx.x;
    int lane = threadIdx.x & 31;
    int c = (n < N_NODES) ? g_deg[n] : 0;
    int v = c;
#pragma unroll
    for (int o = 1; o < 32; o <<= 1) {
        int t = __shfl_up_sync(0xffffffffu, v, o);
        if (lane >= o) v += t;
    }
    int wtotal = __shfl_sync(0xffffffffu, v, 31);
    int base = 0;
    if (lane == 31) base = atomicAdd(&g_total, wtotal);
    base = __shfl_sync(0xffffffffu, base, 31);
    if (n < N_NODES) {
        int start = base + (v - c);
        g_cur[n] = start;
        for (int i = 0; i < c; i++) g_ds[start + i] = n;
    }
}

__global__ void k_scatter(const int* __restrict__ src, const int* __restrict__ dst) {
    int e = blockIdx.x * blockDim.x + threadIdx.x;
    if (e >= N_EDGES) return;
    int d = __ldg(dst + e);
    int pos = atomicAdd(&g_cur[d], 1);
    g_ss[pos] = __ldg(src + e);               // single random 4B store
}

// ---------------- K-edge: sorted stream; 8-lane group owns 64 contiguous edges ----------------
// Per edge: 1 random f-row wavefront. er load only on run break (~1/16);
// acc red.v4 + den red only on break (~1/16 each). f loaded in batches of 4
// (MLP=4/group; 16/warp); REDs clobber-free so loads hoist across flushes.
// Softmax max-pass elided (shift-invariant; |e|=O(0.05)) — validated r1-r11.
__global__ void __launch_bounds__(256) k_edge(
        const float* __restrict__ al,
        float* __restrict__ acc, float* __restrict__ den) {
    int lane = threadIdx.x & 31;
    int warp = (blockIdx.x * blockDim.x + threadIdx.x) >> 5;
    if (warp >= NWARPS) return;
    int sub = lane & 7;                 // float4 slot within 32-float row
    int grp = lane >> 3;                // 8-lane group id
    int head = sub >> 1;
    int gbase = grp << 3;
    int gstart = warp * EDGES_PER_WARP + grp * 64;
    const float4* f4 = (const float4*)g_f;
    float4 sal = __ldg(((const float4*)al) + sub);

    int d_run = -1;
    float er_h = 0.f, den_l = 0.f;
    float4 a_run = make_float4(0.f, 0.f, 0.f, 0.f);

#pragma unroll 1
    for (int o = 0; o < 64; o += 8) {
        int sv = __ldg(g_ss + gstart + o + sub);   // 8 srcs, coalesced per group
        int dv = __ldg(g_ds + gstart + o + sub);
#pragma unroll
        for (int half = 0; half < 2; half++) {
            int s4[4], d4[4];
            float4 fv[4];
#pragma unroll
            for (int j = 0; j < 4; j++) {
                int i = half * 4 + j;
                s4[j] = __shfl_sync(0xffffffffu, sv, gbase + i);
                d4[j] = __shfl_sync(0xffffffffu, dv, gbase + i);
                fv[j] = __ldg(f4 + s4[j] * 8 + sub);   // 4 independent loads
            }
#pragma unroll
            for (int j = 0; j < 4; j++) {
                if (d4[j] != d_run) {                  // rare (~1/16 edges)
                    if (d_run >= 0) {
                        red_add_v4(acc + d_run * 32 + sub * 4, a_run);
                        red_add_f(den + d_run * 8 + sub, den_l);
                    }
                    d_run = d4[j];
                    a_run = make_float4(0.f, 0.f, 0.f, 0.f);
                    den_l = 0.f;
                    er_h = __ldg(g_er + d_run * HEADS + head);
                }
                float part = fv[j].x * sal.x + fv[j].y * sal.y
                           + fv[j].z * sal.z + fv[j].w * sal.w;
                float el = part + __shfl_xor_sync(0xffffffffu, part, 1);
                float x = el + er_h;
                x = x > 0.f ? x : 0.2f * x;            // leaky_relu(0.2)
                float ex = __expf(x);
                a_run.x = fmaf(ex, fv[j].x, a_run.x);
                a_run.y = fmaf(ex, fv[j].y, a_run.y);
                a_run.z = fmaf(ex, fv[j].z, a_run.z);
                a_run.w = fmaf(ex, fv[j].w, a_run.w);
                den_l += ex;
            }
        }
    }
    red_add_v4(acc + d_run * 32 + sub * 4, a_run);
    red_add_f(den + d_run * 8 + sub, den_l);
}

// ---------------- K2: thread-per-node (round-11, frozen) ----------------
__global__ void __launch_bounds__(128) k_node_mid(
        const float* __restrict__ b0,
        const float* __restrict__ W,
        const float* __restrict__ ar) {
    __shared__ float sW[HID * HID];
    __shared__ float sar[HID], sb[HID];
    int tid = threadIdx.x;
    for (int i = tid; i < HID * HID; i += 128) sW[i] = W[i];
    if (tid < HID) { sar[tid] = ar[tid]; sb[tid] = b0[tid]; }
    __syncthreads();

    int n = blockIdx.x * 128 + tid;
    if (n < N_GRAPHS * HID) g_sums[n] = 0.f;
    if (n < N_GRAPHS) g_cnt[n] = 0.f;
    if (n >= N_NODES) return;

    float h[HID];
    const float4* arow = (const float4*)(g_acc0 + (size_t)n * HID);
#pragma unroll
    for (int hh = 0; hh < HEADS; hh++) {
        float dv = g_den0[(size_t)n * 8 + 2 * hh];
        float inv = dv > 0.f ? __fdividef(1.f, dv) : 0.f;
        float4 v0 = arow[2 * hh];
        float4 v1 = arow[2 * hh + 1];
        h[8 * hh]     = fmaxf(fmaf(v0.x, inv, sb[8 * hh]),     0.f);
        h[8 * hh + 1] = fmaxf(fmaf(v0.y, inv, sb[8 * hh + 1]), 0.f);
        h[8 * hh + 2] = fmaxf(fmaf(v0.z, inv, sb[8 * hh + 2]), 0.f);
        h[8 * hh + 3] = fmaxf(fmaf(v0.w, inv, sb[8 * hh + 3]), 0.f);
        h[8 * hh + 4] = fmaxf(fmaf(v1.x, inv, sb[8 * hh + 4]), 0.f);
        h[8 * hh + 5] = fmaxf(fmaf(v1.y, inv, sb[8 * hh + 5]), 0.f);
        h[8 * hh + 6] = fmaxf(fmaf(v1.z, inv, sb[8 * hh + 6]), 0.f);
        h[8 * hh + 7] = fmaxf(fmaf(v1.w, inv, sb[8 * hh + 7]), 0.f);
    }

    float4* fout = (float4*)(g_f + (size_t)n * HID);
    float4* aout = (float4*)(g_acc1 + (size_t)n * HID);
    const float4 z4 = make_float4(0.f, 0.f, 0.f, 0.f);
#pragma unroll
    for (int c = 0; c < 4; c++) {
        float4 fa = z4, fb = z4;
#pragma unroll
        for (int k = 0; k < HID; k++) {
            float hk = h[k];
            const float4* wr = (const float4*)(sW + k * HID) + 2 * c;
            float4 w0 = wr[0];
            float4 w1 = wr[1];
            fa.x = fmaf(hk, w0.x, fa.x); fa.y = fmaf(hk, w0.y, fa.y);
            fa.z = fmaf(hk, w0.z, fa.z); fa.w = fmaf(hk, w0.w, fa.w);
            fb.x = fmaf(hk, w1.x, fb.x); fb.y = fmaf(hk, w1.y, fb.y);
            fb.z = fmaf(hk, w1.z, fb.z); fb.w = fmaf(hk, w1.w, fb.w);
        }
        fout[2 * c]     = fa;
        fout[2 * c + 1] = fb;
        aout[2 * c] = z4; aout[2 * c + 1] = z4;
        float er = fa.x * sar[c * 8]     + fa.y * sar[c * 8 + 1]
                 + fa.z * sar[c * 8 + 2] + fa.w * sar[c * 8 + 3]
                 + fb.x * sar[c * 8 + 4] + fb.y * sar[c * 8 + 5]
                 + fb.z * sar[c * 8 + 6] + fb.w * sar[c * 8 + 7];
        g_er[n * HEADS + c] = er;
    }
    ((float4*)g_den1)[n * 2] = z4;
    ((float4*)g_den1)[n * 2 + 1] = z4;
}

// ---------------- K4: h2 + run-length pooled per-graph sums (graph_ids sorted) ----------------
__global__ void k_pool(const int* __restrict__ graph_ids,
                       const float* __restrict__ b1) {
    int lane = threadIdx.x & 31;
    int warp = (blockIdx.x * blockDim.x + threadIdx.x) >> 5;
    int nwarp = (gridDim.x * blockDim.x) >> 5;
    int dslot = (lane >> 3) << 1;
    float bl = __ldg(b1 + lane);
    int nchunk = (N_NODES + 31) / 32;
    for (int c = warp; c < nchunk; c += nwarp) {
        int base = c * 32;
        int lim = min(32, N_NODES - base);
        float runsum = 0.f;
        int rung = __ldg(graph_ids + base);
        int runcnt = 0;
        for (int i = 0; i < lim; i++) {
            int n = base + i;
            int gid = __ldg(graph_ids + n);            // uniform across warp
            float dv = g_den1[(size_t)n * 8 + dslot];
            float v  = g_acc1[(size_t)n * HID + lane];
            float hv = dv > 0.f ? __fdividef(v, dv) : 0.f;
            hv = fmaxf(hv + bl, 0.f);
            if (gid != rung) {
                atomicAdd(g_sums + rung * HID + lane, runsum);
                if (lane == 0) atomicAdd(g_cnt + rung, (float)runcnt);
                runsum = 0.f; runcnt = 0; rung = gid;
            }
            runsum += hv; runcnt++;
        }
        atomicAdd(g_sums + rung * HID + lane, runsum);
        if (lane == 0) atomicAdd(g_cnt + rung, (float)runcnt);
    }
}

// ---------------- K5: scorer MLP ----------------
__global__ void k_score(const float* __restrict__ sw1, const float* __restrict__ sb1,
                        const float* __restrict__ sw2, const float* __restrict__ sb2,
                        float* __restrict__ out) {
    __shared__ float s1[HID * HID];
    __shared__ float sb[HID], s2[HID];
    int t = threadIdx.x;
    for (int i = t; i < HID * HID; i += blockDim.x) s1[i] = sw1[i];
    if (t < HID) { sb[t] = sb1[t]; s2[t] = sw2[t]; }
    __syncthreads();
    if (t < N_GRAPHS) {
        float c = fmaxf(g_cnt[t], 1.f);
        float invc = __fdividef(1.f, c);
        float hg[HID];
#pragma unroll
        for (int k = 0; k < HID; k++) hg[k] = g_sums[t * HID + k] * invc;
        float score = __ldg(sb2);
#pragma unroll
        for (int j = 0; j < HID; j++) {
            float a = sb[j];
#pragma unroll
            for (int k = 0; k < HID; k++) a += hg[k] * s1[k * HID + j];
            a = fmaxf(a, 0.f);
            score += a * s2[j];
        }
        out[t] = score;
    }
}

// ---------------- launch ----------------
extern "C" void kernel_launch(void* const* d_in, const int* in_sizes, int n_in,
                              void* d_out, int out_size) {
    const int*   node_ids = (const int*)d_in[0];
    const int*   src      = (const int*)d_in[1];
    const int*   dst      = (const int*)d_in[2];
    const int*   gids     = (const int*)d_in[3];
    const float* emb      = (const float*)d_in[4];
    const float* W0       = (const float*)d_in[5];
    const float* al0      = (const float*)d_in[6];
    const float* ar0      = (const float*)d_in[7];
    const float* b0       = (const float*)d_in[8];
    const float* W1       = (const float*)d_in[9];
    const float* al1      = (const float*)d_in[10];
    const float* ar1      = (const float*)d_in[11];
    const float* b1       = (const float*)d_in[12];
    const float* sw1      = (const float*)d_in[13];
    const float* sb1      = (const float*)d_in[14];
    const float* sw2      = (const float*)d_in[15];
    const float* sb2      = (const float*)d_in[16];
    float* out = (float*)d_out;

    void *acc0, *den0, *acc1, *den1;
    cudaGetSymbolAddress(&acc0, g_acc0);
    cudaGetSymbolAddress(&den0, g_den0);
    cudaGetSymbolAddress(&acc1, g_acc1);
    cudaGetSymbolAddress(&den1, g_den1);

    const int nodeBlocks = (N_NODES + 127) / 128;
    const int edgeBlocks = (N_EDGES + 255) / 256;
    const int edgeKBlocks = (NWARPS + 7) / 8;

    k_gather_fc<<<nodeBlocks, 128>>>(node_ids, emb, W0, ar0);
    k_count<<<edgeBlocks, 256>>>(dst);
    k_assign_fill<<<(N_NODES + 255) / 256, 256>>>();
    k_scatter<<<edgeBlocks, 256>>>(src, dst);
    k_edge<<<edgeKBlocks, 256>>>(al0, (float*)acc0, (float*)den0);
    k_node_mid<<<nodeBlocks, 128>>>(b0, W1, ar1);
    k_edge<<<edgeKBlocks, 256>>>(al1, (float*)acc1, (float*)den1);
    k_pool<<<(6250 + 7) / 8, 256>>>(gids, b1);
    k_score<<<1, 64>>>(sw1, sb1, sw2, sb2, out);
}